// round 4
// baseline (speedup 1.0000x reference)
#include <cuda_runtime.h>
#include <cuda_bf16.h>
#include <math.h>

// TemporalAttention: out[d,b] = sum_s softmax_s((enc[b,s,:]·We_w + We_b)*ut)[s] * enc[b,s,d]
// cp.async smem-staged pipeline: loads decoupled from compute.
// Score: 8 threads/row from smem (3-level shuffle). Accum: 1 thread per d column.
// Fused last-CTA-done split merge. No online max (scores bounded, fp32 exp safe).

#define D_DIM   256
#define T_ROWS  32
#define NBUF    3
#define NSPLIT  16
#define THREADS 256
#define MAXB    128

#define TILE_F4   (T_ROWS * D_DIM / 4)   // 2048 float4 per tile
#define BUF_FLOATS (T_ROWS * D_DIM)      // 8192 floats per buffer
#define SMEM_BYTES (NBUF * BUF_FLOATS * 4 + T_ROWS * 4)

// Per-(b,split) partial: 256 acc values + l (+1 pad)
__device__ float        g_scratch[MAXB * NSPLIT * (D_DIM + 2)];
__device__ unsigned int g_cnt[MAXB];   // zero-init; reset by merger each launch

__device__ __forceinline__ unsigned smem_u32(const void* p) {
    return (unsigned)__cvta_generic_to_shared(p);
}
__device__ __forceinline__ void cp_async16(unsigned s, const void* g) {
    asm volatile("cp.async.cg.shared.global [%0], [%1], 16;\n" :: "r"(s), "l"(g));
}
__device__ __forceinline__ void cp_commit() {
    asm volatile("cp.async.commit_group;\n");
}
template<int N> __device__ __forceinline__ void cp_wait() {
    asm volatile("cp.async.wait_group %0;\n" :: "n"(N));
}

__device__ __forceinline__ void issue_tile(float* bufs, const float* base,
                                           int tile, int rows, int t)
{
    float* buf = bufs + (tile % NBUF) * BUF_FLOATS;
    const float4* g = (const float4*)(base + (long long)tile * T_ROWS * D_DIM);
    const int rv = min(T_ROWS, rows - tile * T_ROWS);
#pragma unroll
    for (int i = 0; i < TILE_F4 / THREADS; i++) {
        int idx = t + i * THREADS;          // float4 index within tile
        int row = idx >> 6;                 // 64 float4 per row
        if (row < rv)
            cp_async16(smem_u32((float4*)buf + idx), g + idx);
    }
    cp_commit();
}

__global__ __launch_bounds__(THREADS, 2) void ta_fused(
    const float* __restrict__ enc,
    const float* __restrict__ Ww,
    const float* __restrict__ Wb,
    const float* __restrict__ ut,
    float* __restrict__ out,
    int S, int B)
{
    extern __shared__ float smem[];
    float* bufs = smem;                       // NBUF * 32 * 256 floats
    float* pbuf = smem + NBUF * BUF_FLOATS;   // 32 floats

    const int split = blockIdx.x;
    const int b     = blockIdx.y;
    const int t     = threadIdx.x;
    const int part  = t & 7;    // 8 threads per row
    const int row8  = t >> 3;   // 0..31: score row

    // Thread's 32 w columns: part*4 + j*32 (strided float4 -> bank-conflict-free)
    float4 wv[8];
#pragma unroll
    for (int j = 0; j < 8; j++) wv[j] = ((const float4*)Ww)[part + j * 8];
    const float be = Wb[0];
    const float u  = ut[0];

    const int s0   = (int)(((long long)split * S) / NSPLIT);
    const int s1   = (int)(((long long)(split + 1) * S) / NSPLIT);
    const int rows = s1 - s0;
    const float* base = enc + ((long long)b * S + s0) * D_DIM;

    const int ntiles = (rows + T_ROWS - 1) / T_ROWS;

    // Prime the pipeline
    int issued = 0;
    while (issued < NBUF - 1 && issued < ntiles) { issue_tile(bufs, base, issued, rows, t); issued++; }

    float acc = 0.0f;   // this thread's d = t column
    float l   = 0.0f;

    for (int k = 0; k < ntiles; k++) {
        // Ensure tile k's group is complete
        if (issued - k - 1 >= 1) cp_wait<1>(); else cp_wait<0>();
        __syncthreads();   // buffer k visible to all threads

        float* buf = bufs + (k % NBUF) * BUF_FLOATS;
        const int rv = min(T_ROWS, rows - k * T_ROWS);

        // ---- score phase: 8 threads per row, strided columns ----
        if (row8 < rv) {
            const float4* rp = (const float4*)(buf + row8 * D_DIM);
            float d = 0.0f;
#pragma unroll
            for (int j = 0; j < 8; j++) {
                float4 x = rp[part + j * 8];
                d = fmaf(x.x, wv[j].x, fmaf(x.y, wv[j].y,
                    fmaf(x.z, wv[j].z, fmaf(x.w, wv[j].w, d))));
            }
            d += __shfl_xor_sync(0xffffffffu, d, 1);
            d += __shfl_xor_sync(0xffffffffu, d, 2);
            d += __shfl_xor_sync(0xffffffffu, d, 4);
            if (part == 0) pbuf[row8] = __expf((d + be) * u);
        } else if (part == 0) {
            pbuf[row8] = 0.0f;
        }
        __syncthreads();   // p ready

        // ---- accum phase: thread t owns column d = t ----
        const float* col = buf + t;
        if (rv == T_ROWS) {
            float4 pv[8];
#pragma unroll
            for (int j = 0; j < 8; j++) pv[j] = ((const float4*)pbuf)[j];
#pragma unroll
            for (int j = 0; j < 8; j++) {
                acc = fmaf(pv[j].x, col[(j * 4 + 0) * D_DIM], acc);
                acc = fmaf(pv[j].y, col[(j * 4 + 1) * D_DIM], acc);
                acc = fmaf(pv[j].z, col[(j * 4 + 2) * D_DIM], acc);
                acc = fmaf(pv[j].w, col[(j * 4 + 3) * D_DIM], acc);
                l += (pv[j].x + pv[j].y) + (pv[j].z + pv[j].w);
            }
        } else {
            for (int s = 0; s < rv; s++) {
                float p = pbuf[s];
                acc = fmaf(p, col[s * D_DIM], acc);
                l += p;
            }
        }

        // ---- prefetch next tile into the buffer freed 2 iterations ago ----
        if (issued < ntiles) { issue_tile(bufs, base, issued, rows, t); issued++; }
    }

    // ---- write partial for this (b, split) ----
    float* o = g_scratch + ((long long)(b * NSPLIT + split)) * (D_DIM + 2);
    o[t] = acc;
    if (t == 0) o[D_DIM] = l;   // all threads hold identical l

    // ---- fused split-merge: last CTA per batch sums all NSPLIT partials ----
    __threadfence();
    __syncthreads();
    __shared__ unsigned int s_last;
    if (t == 0) s_last = (atomicAdd(&g_cnt[b], 1u) == (unsigned)(NSPLIT - 1));
    __syncthreads();
    if (!s_last) return;

    const float* sc = g_scratch + (long long)b * NSPLIT * (D_DIM + 2);
    float Lg = 0.0f, ag = 0.0f;
#pragma unroll
    for (int i = 0; i < NSPLIT; i++) {
        Lg += sc[i * (D_DIM + 2) + D_DIM];
        ag += sc[i * (D_DIM + 2) + t];
    }
    out[t * B + b] = ag / Lg;   // out is [D, B]

    if (t == 0) g_cnt[b] = 0;   // reset for next graph replay
}

extern "C" void kernel_launch(void* const* d_in, const int* in_sizes, int n_in,
                              void* d_out, int out_size)
{
    const float* enc = (const float*)d_in[0];
    const float* Ww  = (const float*)d_in[1];
    const float* Wb  = (const float*)d_in[2];
    const float* ut  = (const float*)d_in[3];
    float* out = (float*)d_out;

    const int D = in_sizes[1];           // 256
    const int B = out_size / D;          // 64
    const int S = in_sizes[0] / (B * D); // 4096

    cudaFuncSetAttribute(ta_fused, cudaFuncAttributeMaxDynamicSharedMemorySize, SMEM_BYTES);

    dim3 grid(NSPLIT, B);
    ta_fused<<<grid, THREADS, SMEM_BYTES>>>(enc, Ww, Wb, ut, out, S, B);
}